// round 6
// baseline (speedup 1.0000x reference)
#include <cuda_runtime.h>
#include <cuda_bf16.h>

// Problem constants (GCN_55499567399154)
#define NMAX 50000
#define EMAX 800000
#define FIN  128
#define HID  128
#define NCLS 64

// ---------------- static scratch (no allocations allowed) ----------------
// Device-global symbols are ONLY referenced from device code.
__device__ __align__(256) float d_bufX[NMAX * HID];   // node features (layer input)
__device__ __align__(256) float d_bufG[NMAX * HID];   // g = dinv * (X @ W)
__device__ __align__(256) float d_dinv[NMAX];
__device__ __align__(256) int   d_deg[NMAX];
__device__ __align__(256) int   d_off[NMAX + 8];
__device__ __align__(256) int   d_cur[NMAX];
__device__ __align__(256) int   d_csr[EMAX];
__device__ __align__(256) int   d_bsum[512];
__device__ int d_is64;   // 1 if edge_index is int64, 0 if int32

// ---------------- f32x2 helpers (PTX-only packed FMA path) ----------------
__device__ __forceinline__ unsigned long long pack2(float x, float y) {
    unsigned long long r;
    asm("mov.b64 %0, {%1,%2};" : "=l"(r) : "f"(x), "f"(y));
    return r;
}
__device__ __forceinline__ void unpack2(unsigned long long v, float& lo, float& hi) {
    asm("mov.b64 {%0,%1}, %2;" : "=f"(lo), "=f"(hi) : "l"(v));
}
__device__ __forceinline__ unsigned long long ffma2(unsigned long long a,
                                                    unsigned long long b,
                                                    unsigned long long c) {
    unsigned long long d;
    asm("fma.rn.f32x2 %0, %1, %2, %3;" : "=l"(d) : "l"(a), "l"(b), "l"(c));
    return d;
}

// ---------------- edge index dtype detection + accessors ----------------
__global__ void detect_kernel(const int* __restrict__ p, int E) {
    if (blockIdx.x == 0 && threadIdx.x == 0) {
        int is64 = 1;
        int cnt = (E < 256) ? E : 256;
        for (int i = 0; i < cnt; i++)
            if (p[2 * i + 1] != 0) { is64 = 0; break; }
        d_is64 = is64;
    }
}

__device__ __forceinline__ int edge_src(const int* p, int E, int e) {
    return d_is64 ? p[2 * e] : p[e];
}
__device__ __forceinline__ int edge_dst(const int* p, int E, int e) {
    return d_is64 ? p[2 * (E + e)] : p[E + e];
}

// ---------------- graph build ----------------
__global__ void deg_init_kernel(int n) {
    int i = blockIdx.x * blockDim.x + threadIdx.x;
    if (i < n) d_deg[i] = 1;  // self-loop
}

__global__ void hist_kernel(const int* __restrict__ ei, int E) {
    int e = blockIdx.x * blockDim.x + threadIdx.x;
    if (e < E) atomicAdd(&d_deg[edge_dst(ei, E, e)], 1);
}

// exclusive scan of (deg-1) -> d_off (CSR holds real edges only)
__global__ void scan1_kernel(int n) {
    __shared__ int sh[512];
    int tid = threadIdx.x;
    int i = blockIdx.x * 512 + tid;
    int v = (i < n) ? (d_deg[i] - 1) : 0;
    sh[tid] = v;
    __syncthreads();
#pragma unroll
    for (int dlt = 1; dlt < 512; dlt <<= 1) {
        int t = (tid >= dlt) ? sh[tid - dlt] : 0;
        __syncthreads();
        sh[tid] += t;
        __syncthreads();
    }
    if (i < n) d_off[i] = sh[tid] - v;            // block-local exclusive
    if (tid == 511) d_bsum[blockIdx.x] = sh[511]; // block total
}

__global__ void scan2_kernel(int nb, int n) {
    __shared__ int sh[512];
    int tid = threadIdx.x;
    int v = (tid < nb) ? d_bsum[tid] : 0;
    sh[tid] = v;
    __syncthreads();
#pragma unroll
    for (int dlt = 1; dlt < 512; dlt <<= 1) {
        int t = (tid >= dlt) ? sh[tid - dlt] : 0;
        __syncthreads();
        sh[tid] += t;
        __syncthreads();
    }
    if (tid < nb) d_bsum[tid] = sh[tid] - v;  // exclusive block bases
    if (tid == 0) d_off[n] = sh[511];         // grand total = E
}

__global__ void scan3_kernel(int n) {
    int i = blockIdx.x * blockDim.x + threadIdx.x;
    if (i < n) {
        int o = d_off[i] + d_bsum[i >> 9];
        d_off[i] = o;
        d_cur[i] = o;
        d_dinv[i] = rsqrtf((float)d_deg[i]);
    }
}

__global__ void fill_kernel(const int* __restrict__ ei, int E) {
    int e = blockIdx.x * blockDim.x + threadIdx.x;
    if (e < E) {
        int c = edge_dst(ei, E, e);
        int p = atomicAdd(&d_cur[c], 1);
        d_csr[p] = edge_src(ei, E, e);
    }
}

// ---------------- GEMM: G = dinv .* (X @ W), K=128, OUT = 16*TN ----------------
// block tile: 128 rows x OUT cols, 256 threads, per-thread 8 x TN via fma.rn.f32x2
// SRC_GLOBAL: read X from internal d_bufX (device symbol) instead of param.
template <int TN, bool SRC_GLOBAL>
__global__ void __launch_bounds__(256) gemm_scale_kernel(
    const float* __restrict__ Xparam, const float* __restrict__ W, int n) {
    constexpr int OUT = 16 * TN;
    constexpr int K = 128;
    constexpr int BK = 32;
    __shared__ float Xs[BK][132];   // transposed: Xs[k][r], pad for banks
    __shared__ float Ws[BK][OUT];   // Ws[k][c]

    const float* X = SRC_GLOBAL ? d_bufX : Xparam;

    const int t = threadIdx.x;
    const int ty = t >> 4;   // 0..15 : rows ty*8..+8
    const int tx = t & 15;   // 0..15 : cols tx*TN..+TN
    const int row0 = blockIdx.x * 128;

    unsigned long long acc[8][TN / 2];
#pragma unroll
    for (int i = 0; i < 8; i++)
#pragma unroll
        for (int j = 0; j < TN / 2; j++) acc[i][j] = 0ull;

    for (int kb = 0; kb < K; kb += BK) {
        // load X chunk (128 rows x 32 k), transpose into smem
#pragma unroll
        for (int it = 0; it < 4; ++it) {
            int v = t + it * 256;      // 0..1023 float4 slots
            int r = v >> 3;            // 8 float4 per row
            int kq = v & 7;
            float4 val = make_float4(0.f, 0.f, 0.f, 0.f);
            int gr = row0 + r;
            if (gr < n) val = *(const float4*)(X + (size_t)gr * K + kb + kq * 4);
            Xs[kq * 4 + 0][r] = val.x;
            Xs[kq * 4 + 1][r] = val.y;
            Xs[kq * 4 + 2][r] = val.z;
            Xs[kq * 4 + 3][r] = val.w;
        }
        // load W chunk (32 x OUT)
#pragma unroll
        for (int it = 0; it < (BK * OUT / 4) / 256; ++it) {
            int v = t + it * 256;
            int k = v / (OUT / 4);
            int c4 = v % (OUT / 4);
            *(float4*)&Ws[k][c4 * 4] =
                *(const float4*)(W + (size_t)(kb + k) * OUT + c4 * 4);
        }
        __syncthreads();

#pragma unroll
        for (int k = 0; k < BK; ++k) {
            float4 a0 = *(const float4*)&Xs[k][ty * 8];
            float4 a1 = *(const float4*)&Xs[k][ty * 8 + 4];
            float a[8] = {a0.x, a0.y, a0.z, a0.w, a1.x, a1.y, a1.z, a1.w};
            unsigned long long w2[TN / 2];
#pragma unroll
            for (int j = 0; j < TN / 2; j++)
                w2[j] = *(const unsigned long long*)&Ws[k][tx * TN + 2 * j];
#pragma unroll
            for (int i = 0; i < 8; i++) {
                unsigned long long a2 = pack2(a[i], a[i]);
#pragma unroll
                for (int j = 0; j < TN / 2; j++)
                    acc[i][j] = ffma2(a2, w2[j], acc[i][j]);
            }
        }
        __syncthreads();
    }

    // epilogue: scale by dinv[row] and store to d_bufG (stride OUT)
#pragma unroll
    for (int i = 0; i < 8; i++) {
        int gr = row0 + ty * 8 + i;
        if (gr < n) {
            float dv = d_dinv[gr];
            float o[TN];
#pragma unroll
            for (int j = 0; j < TN / 2; j++) {
                float lo, hi;
                unpack2(acc[i][j], lo, hi);
                o[2 * j] = lo * dv;
                o[2 * j + 1] = hi * dv;
            }
            float* dst = d_bufG + (size_t)gr * OUT + tx * TN;
#pragma unroll
            for (int q = 0; q < TN / 4; q++)
                *(float4*)(dst + 4 * q) =
                    make_float4(o[4 * q], o[4 * q + 1], o[4 * q + 2], o[4 * q + 3]);
        }
    }
}

// ---------------- aggregation: Y[c] = relu?(dinv[c]*(sum_in g + g[c]) + b) ----------------
// OUT_PARAM: write to Yparam (harness buffer) instead of internal d_bufX.
template <int F, bool RELU, bool OUT_PARAM>
__global__ void __launch_bounds__(256) agg_kernel(
    const float* __restrict__ bias, float* __restrict__ Yparam, int n) {
    constexpr int V = F / 32;  // floats per lane (4 or 2)
    int gw = (blockIdx.x * 256 + threadIdx.x) >> 5;
    int lane = threadIdx.x & 31;
    if (gw >= n) return;

    float* Y = OUT_PARAM ? Yparam : d_bufX;
    const float* gbase = d_bufG;

    float acc0, acc1, acc2, acc3;
    const float* self = gbase + (size_t)gw * F + lane * V;
    if constexpr (V == 4) {
        float4 tv = *(const float4*)self;
        acc0 = tv.x; acc1 = tv.y; acc2 = tv.z; acc3 = tv.w;
    } else {
        float2 tv = *(const float2*)self;
        acc0 = tv.x; acc1 = tv.y; acc2 = 0.f; acc3 = 0.f;
    }

    int s = d_off[gw];
    int e = d_off[gw + 1];
    int j = s;
    for (; j + 1 < e; j += 2) {
        int r0 = d_csr[j];
        int r1 = d_csr[j + 1];
        if constexpr (V == 4) {
            float4 v0 = *(const float4*)(gbase + (size_t)r0 * F + lane * 4);
            float4 v1 = *(const float4*)(gbase + (size_t)r1 * F + lane * 4);
            acc0 += v0.x; acc1 += v0.y; acc2 += v0.z; acc3 += v0.w;
            acc0 += v1.x; acc1 += v1.y; acc2 += v1.z; acc3 += v1.w;
        } else {
            float2 v0 = *(const float2*)(gbase + (size_t)r0 * F + lane * 2);
            float2 v1 = *(const float2*)(gbase + (size_t)r1 * F + lane * 2);
            acc0 += v0.x; acc1 += v0.y;
            acc0 += v1.x; acc1 += v1.y;
        }
    }
    if (j < e) {
        int r0 = d_csr[j];
        if constexpr (V == 4) {
            float4 v0 = *(const float4*)(gbase + (size_t)r0 * F + lane * 4);
            acc0 += v0.x; acc1 += v0.y; acc2 += v0.z; acc3 += v0.w;
        } else {
            float2 v0 = *(const float2*)(gbase + (size_t)r0 * F + lane * 2);
            acc0 += v0.x; acc1 += v0.y;
        }
    }

    float dv = d_dinv[gw];
    float* dst = Y + (size_t)gw * F + lane * V;
    if constexpr (V == 4) {
        float4 bv = *(const float4*)(bias + lane * 4);
        float4 o;
        o.x = dv * acc0 + bv.x;
        o.y = dv * acc1 + bv.y;
        o.z = dv * acc2 + bv.z;
        o.w = dv * acc3 + bv.w;
        if (RELU) {
            o.x = fmaxf(o.x, 0.f); o.y = fmaxf(o.y, 0.f);
            o.z = fmaxf(o.z, 0.f); o.w = fmaxf(o.w, 0.f);
        }
        *(float4*)dst = o;
    } else {
        float2 bv = *(const float2*)(bias + lane * 2);
        float2 o;
        o.x = dv * acc0 + bv.x;
        o.y = dv * acc1 + bv.y;
        if (RELU) { o.x = fmaxf(o.x, 0.f); o.y = fmaxf(o.y, 0.f); }
        *(float2*)dst = o;
    }
}

// ---------------- launch ----------------
extern "C" void kernel_launch(void* const* d_in, const int* in_sizes, int n_in,
                              void* d_out, int out_size) {
    const float* x  = (const float*)d_in[0];
    const int*   ei = (const int*)d_in[1];   // int32 or int64 words; auto-detected
    const float* W1 = (const float*)d_in[2];
    const float* b1 = (const float*)d_in[3];
    const float* W2 = (const float*)d_in[4];
    const float* b2 = (const float*)d_in[5];
    const float* W3 = (const float*)d_in[6];
    const float* b3 = (const float*)d_in[7];
    const float* W4 = (const float*)d_in[8];
    const float* b4 = (const float*)d_in[9];
    float* out = (float*)d_out;

    int n = in_sizes[0] / FIN;
    int E = in_sizes[1] / 2;

    // graph build
    detect_kernel<<<1, 32>>>(ei, E);
    deg_init_kernel<<<(n + 255) / 256, 256>>>(n);
    hist_kernel<<<(E + 255) / 256, 256>>>(ei, E);
    int nb = (n + 511) / 512;
    scan1_kernel<<<nb, 512>>>(n);
    scan2_kernel<<<1, 512>>>(nb, n);
    scan3_kernel<<<(n + 255) / 256, 256>>>(n);
    fill_kernel<<<(E + 255) / 256, 256>>>(ei, E);

    int gemm_blocks = (n + 127) / 128;
    int agg_blocks = (n * 32 + 255) / 256;

    // layer 1: x -> bufX (internal)
    gemm_scale_kernel<8, false><<<gemm_blocks, 256>>>(x, W1, n);
    agg_kernel<128, true, false><<<agg_blocks, 256>>>(b1, nullptr, n);
    // layer 2
    gemm_scale_kernel<8, true><<<gemm_blocks, 256>>>(nullptr, W2, n);
    agg_kernel<128, true, false><<<agg_blocks, 256>>>(b2, nullptr, n);
    // layer 3
    gemm_scale_kernel<8, true><<<gemm_blocks, 256>>>(nullptr, W3, n);
    agg_kernel<128, true, false><<<agg_blocks, 256>>>(b3, nullptr, n);
    // layer 4 (OUT=64) -> d_out
    gemm_scale_kernel<4, true><<<gemm_blocks, 256>>>(nullptr, W4, n);
    agg_kernel<64, false, true><<<agg_blocks, 256>>>(b4, out, n);
}

// round 7
// speedup vs baseline: 1.0781x; 1.0781x over previous
#include <cuda_runtime.h>
#include <cuda_fp16.h>
#include <cuda_bf16.h>

// Problem constants (GCN_55499567399154)
#define NMAX 50000
#define EMAX 800000
#define FIN  128
#define HID  128
#define NCLS 64

// ---------------- static scratch (no allocations allowed) ----------------
// Device-global symbols are ONLY referenced from device code.
__device__ __align__(256) float  d_bufX[NMAX * HID];  // node features (layer input, fp32)
__device__ __align__(256) __half d_bufG[NMAX * HID];  // g = dinv * (X @ W), fp16 storage
__device__ __align__(256) float  d_dinv[NMAX];
__device__ __align__(256) int    d_deg[NMAX];
__device__ __align__(256) int    d_off[NMAX + 8];
__device__ __align__(256) int    d_cur[NMAX];
__device__ __align__(256) int    d_csr[EMAX];
__device__ __align__(256) int    d_bsum[512];
__device__ int d_is64;   // 1 if edge_index is int64, 0 if int32

// ---------------- edge index dtype detection + accessors ----------------
__global__ void detect_kernel(const int* __restrict__ p, int E) {
    if (blockIdx.x == 0 && threadIdx.x == 0) {
        int is64 = 1;
        int cnt = (E < 256) ? E : 256;
        for (int i = 0; i < cnt; i++)
            if (p[2 * i + 1] != 0) { is64 = 0; break; }
        d_is64 = is64;
    }
}

__device__ __forceinline__ int edge_src(const int* p, int E, int e) {
    return d_is64 ? p[2 * e] : p[e];
}
__device__ __forceinline__ int edge_dst(const int* p, int E, int e) {
    return d_is64 ? p[2 * (E + e)] : p[E + e];
}

// ---------------- graph build ----------------
__global__ void deg_init_kernel(int n) {
    int i = blockIdx.x * blockDim.x + threadIdx.x;
    if (i < n) d_deg[i] = 1;  // self-loop
}

__global__ void hist_kernel(const int* __restrict__ ei, int E) {
    int e = blockIdx.x * blockDim.x + threadIdx.x;
    if (e < E) atomicAdd(&d_deg[edge_dst(ei, E, e)], 1);
}

// exclusive scan of (deg-1) -> d_off (CSR holds real edges only)
__global__ void scan1_kernel(int n) {
    __shared__ int sh[512];
    int tid = threadIdx.x;
    int i = blockIdx.x * 512 + tid;
    int v = (i < n) ? (d_deg[i] - 1) : 0;
    sh[tid] = v;
    __syncthreads();
#pragma unroll
    for (int dlt = 1; dlt < 512; dlt <<= 1) {
        int t = (tid >= dlt) ? sh[tid - dlt] : 0;
        __syncthreads();
        sh[tid] += t;
        __syncthreads();
    }
    if (i < n) d_off[i] = sh[tid] - v;            // block-local exclusive
    if (tid == 511) d_bsum[blockIdx.x] = sh[511]; // block total
}

__global__ void scan2_kernel(int nb, int n) {
    __shared__ int sh[512];
    int tid = threadIdx.x;
    int v = (tid < nb) ? d_bsum[tid] : 0;
    sh[tid] = v;
    __syncthreads();
#pragma unroll
    for (int dlt = 1; dlt < 512; dlt <<= 1) {
        int t = (tid >= dlt) ? sh[tid - dlt] : 0;
        __syncthreads();
        sh[tid] += t;
        __syncthreads();
    }
    if (tid < nb) d_bsum[tid] = sh[tid] - v;  // exclusive block bases
    if (tid == 0) d_off[n] = sh[511];         // grand total = E
}

__global__ void scan3_kernel(int n) {
    int i = blockIdx.x * blockDim.x + threadIdx.x;
    if (i < n) {
        int o = d_off[i] + d_bsum[i >> 9];
        d_off[i] = o;
        d_cur[i] = o;
        d_dinv[i] = rsqrtf((float)d_deg[i]);
    }
}

__global__ void fill_kernel(const int* __restrict__ ei, int E) {
    int e = blockIdx.x * blockDim.x + threadIdx.x;
    if (e < E) {
        int c = edge_dst(ei, E, e);
        int p = atomicAdd(&d_cur[c], 1);
        d_csr[p] = edge_src(ei, E, e);
    }
}

// ---------------- GEMM: G = fp16( dinv .* (X @ W) ), K=128, OUT = 16*TN ----------------
// block tile: 128 rows x OUT cols, 256 threads, per-thread 8 x TN fp32 FFMA.
// SRC_GLOBAL: read X from internal d_bufX (device symbol) instead of param.
template <int TN, bool SRC_GLOBAL>
__global__ void __launch_bounds__(256) gemm_scale_kernel(
    const float* __restrict__ Xparam, const float* __restrict__ W, int n) {
    constexpr int OUT = 16 * TN;
    constexpr int K = 128;
    constexpr int BK = 32;
    __shared__ float Xs[BK][132];   // transposed: Xs[k][r], pad for banks
    __shared__ float Ws[BK][OUT];   // Ws[k][c]

    const float* X = SRC_GLOBAL ? d_bufX : Xparam;

    const int t = threadIdx.x;
    const int ty = t >> 4;   // 0..15 : rows ty*8..+8
    const int tx = t & 15;   // 0..15 : cols tx*TN..+TN
    const int row0 = blockIdx.x * 128;

    float acc[8][TN];
#pragma unroll
    for (int i = 0; i < 8; i++)
#pragma unroll
        for (int j = 0; j < TN; j++) acc[i][j] = 0.f;

    for (int kb = 0; kb < K; kb += BK) {
        // load X chunk (128 rows x 32 k), transpose into smem
#pragma unroll
        for (int it = 0; it < 4; ++it) {
            int v = t + it * 256;      // 0..1023 float4 slots
            int r = v >> 3;            // 8 float4 per row
            int kq = v & 7;
            float4 val = make_float4(0.f, 0.f, 0.f, 0.f);
            int gr = row0 + r;
            if (gr < n) val = *(const float4*)(X + (size_t)gr * K + kb + kq * 4);
            Xs[kq * 4 + 0][r] = val.x;
            Xs[kq * 4 + 1][r] = val.y;
            Xs[kq * 4 + 2][r] = val.z;
            Xs[kq * 4 + 3][r] = val.w;
        }
        // load W chunk (32 x OUT)
#pragma unroll
        for (int it = 0; it < (BK * OUT / 4) / 256; ++it) {
            int v = t + it * 256;
            int k = v / (OUT / 4);
            int c4 = v % (OUT / 4);
            *(float4*)&Ws[k][c4 * 4] =
                *(const float4*)(W + (size_t)(kb + k) * OUT + c4 * 4);
        }
        __syncthreads();

#pragma unroll
        for (int k = 0; k < BK; ++k) {
            float4 a0 = *(const float4*)&Xs[k][ty * 8];
            float4 a1 = *(const float4*)&Xs[k][ty * 8 + 4];
            float a[8] = {a0.x, a0.y, a0.z, a0.w, a1.x, a1.y, a1.z, a1.w};
            float w[TN];
#pragma unroll
            for (int j = 0; j < TN / 4; j++) {
                float4 wv = *(const float4*)&Ws[k][tx * TN + 4 * j];
                w[4 * j + 0] = wv.x; w[4 * j + 1] = wv.y;
                w[4 * j + 2] = wv.z; w[4 * j + 3] = wv.w;
            }
#pragma unroll
            for (int i = 0; i < 8; i++)
#pragma unroll
                for (int j = 0; j < TN; j++)
                    acc[i][j] = fmaf(a[i], w[j], acc[i][j]);
        }
        __syncthreads();
    }

    // epilogue: scale by dinv[row], convert to fp16, store to d_bufG (stride OUT)
#pragma unroll
    for (int i = 0; i < 8; i++) {
        int gr = row0 + ty * 8 + i;
        if (gr < n) {
            float dv = d_dinv[gr];
            __half2 h[TN / 2];
#pragma unroll
            for (int j = 0; j < TN / 2; j++)
                h[j] = __floats2half2_rn(acc[i][2 * j] * dv, acc[i][2 * j + 1] * dv);
            __half* dst = d_bufG + (size_t)gr * OUT + tx * TN;
            if constexpr (TN == 8) {
                uint4 v;
                v.x = *(unsigned int*)&h[0];
                v.y = *(unsigned int*)&h[1];
                v.z = *(unsigned int*)&h[2];
                v.w = *(unsigned int*)&h[3];
                *(uint4*)dst = v;
            } else {  // TN == 4
                uint2 v;
                v.x = *(unsigned int*)&h[0];
                v.y = *(unsigned int*)&h[1];
                *(uint2*)dst = v;
            }
        }
    }
}

// ---------------- aggregation: Y[c] = relu?(dinv[c]*(sum_in g + g[c]) + b) ----------------
// g rows are fp16; accumulate fp32. One warp per node.
// OUT_PARAM: write to Yparam (harness buffer) instead of internal d_bufX.
template <int F, bool RELU, bool OUT_PARAM>
__global__ void __launch_bounds__(256) agg_kernel(
    const float* __restrict__ bias, float* __restrict__ Yparam, int n) {
    constexpr int V = F / 32;  // features per lane (4 or 2)
    int gw = (blockIdx.x * 256 + threadIdx.x) >> 5;
    int lane = threadIdx.x & 31;
    if (gw >= n) return;

    float* Y = OUT_PARAM ? Yparam : d_bufX;
    const __half* gbase = d_bufG;

    float acc0 = 0.f, acc1 = 0.f, acc2 = 0.f, acc3 = 0.f;
    // self contribution
    {
        const __half* self = gbase + (size_t)gw * F + lane * V;
        if constexpr (V == 4) {
            uint2 rv = *(const uint2*)self;
            float2 f0 = __half22float2(*(const __half2*)&rv.x);
            float2 f1 = __half22float2(*(const __half2*)&rv.y);
            acc0 = f0.x; acc1 = f0.y; acc2 = f1.x; acc3 = f1.y;
        } else {
            unsigned int rv = *(const unsigned int*)self;
            float2 f0 = __half22float2(*(const __half2*)&rv);
            acc0 = f0.x; acc1 = f0.y;
        }
    }

    int s = d_off[gw];
    int e = d_off[gw + 1];
    int j = s;
    for (; j + 1 < e; j += 2) {
        int r0 = d_csr[j];
        int r1 = d_csr[j + 1];
        if constexpr (V == 4) {
            uint2 v0 = *(const uint2*)(gbase + (size_t)r0 * F + lane * 4);
            uint2 v1 = *(const uint2*)(gbase + (size_t)r1 * F + lane * 4);
            float2 a0 = __half22float2(*(const __half2*)&v0.x);
            float2 a1 = __half22float2(*(const __half2*)&v0.y);
            float2 b0 = __half22float2(*(const __half2*)&v1.x);
            float2 b1 = __half22float2(*(const __half2*)&v1.y);
            acc0 += a0.x + b0.x; acc1 += a0.y + b0.y;
            acc2 += a1.x + b1.x; acc3 += a1.y + b1.y;
        } else {
            unsigned int v0 = *(const unsigned int*)(gbase + (size_t)r0 * F + lane * 2);
            unsigned int v1 = *(const unsigned int*)(gbase + (size_t)r1 * F + lane * 2);
            float2 a0 = __half22float2(*(const __half2*)&v0);
            float2 b0 = __half22float2(*(const __half2*)&v1);
            acc0 += a0.x + b0.x; acc1 += a0.y + b0.y;
        }
    }
    if (j < e) {
        int r0 = d_csr[j];
        if constexpr (V == 4) {
            uint2 v0 = *(const uint2*)(gbase + (size_t)r0 * F + lane * 4);
            float2 a0 = __half22float2(*(const __half2*)&v0.x);
            float2 a1 = __half22float2(*(const __half2*)&v0.y);
            acc0 += a0.x; acc1 += a0.y; acc2 += a1.x; acc3 += a1.y;
        } else {
            unsigned int v0 = *(const unsigned int*)(gbase + (size_t)r0 * F + lane * 2);
            float2 a0 = __half22float2(*(const __half2*)&v0);
            acc0 += a0.x; acc1 += a0.y;
        }
    }

    float dv = d_dinv[gw];
    float* dst = Y + (size_t)gw * F + lane * V;
    if constexpr (V == 4) {
        float4 bv = *(const float4*)(bias + lane * 4);
        float4 o;
        o.x = dv * acc0 + bv.x;
        o.y = dv * acc1 + bv.y;
        o.z = dv * acc2 + bv.z;
        o.w = dv * acc3 + bv.w;
        if (RELU) {
            o.x = fmaxf(o.x, 0.f); o.y = fmaxf(o.y, 0.f);
            o.z = fmaxf(o.z, 0.f); o.w = fmaxf(o.w, 0.f);
        }
        *(float4*)dst = o;
    } else {
        float2 bv = *(const float2*)(bias + lane * 2);
        float2 o;
        o.x = dv * acc0 + bv.x;
        o.y = dv * acc1 + bv.y;
        if (RELU) { o.x = fmaxf(o.x, 0.f); o.y = fmaxf(o.y, 0.f); }
        *(float2*)dst = o;
    }
}

// ---------------- launch ----------------
extern "C" void kernel_launch(void* const* d_in, const int* in_sizes, int n_in,
                              void* d_out, int out_size) {
    const float* x  = (const float*)d_in[0];
    const int*   ei = (const int*)d_in[1];   // int32 or int64 words; auto-detected
    const float* W1 = (const float*)d_in[2];
    const float* b1 = (const float*)d_in[3];
    const float* W2 = (const float*)d_in[4];
    const float* b2 = (const float*)d_in[5];
    const float* W3 = (const float*)d_in[6];
    const float* b3 = (const float*)d_in[7];
    const float* W4 = (const float*)d_in[8];
    const float* b4 = (const float*)d_in[9];
    float* out = (float*)d_out;

    int n = in_sizes[0] / FIN;
    int E = in_sizes[1] / 2;

    // graph build
    detect_kernel<<<1, 32>>>(ei, E);
    deg_init_kernel<<<(n + 255) / 256, 256>>>(n);
    hist_kernel<<<(E + 255) / 256, 256>>>(ei, E);
    int nb = (n + 511) / 512;
    scan1_kernel<<<nb, 512>>>(n);
    scan2_kernel<<<1, 512>>>(nb, n);
    scan3_kernel<<<(n + 255) / 256, 256>>>(n);
    fill_kernel<<<(E + 255) / 256, 256>>>(ei, E);

    int gemm_blocks = (n + 127) / 128;
    int agg_blocks = (n * 32 + 255) / 256;

    // layer 1: x -> bufX (internal)
    gemm_scale_kernel<8, false><<<gemm_blocks, 256>>>(x, W1, n);
    agg_kernel<128, true, false><<<agg_blocks, 256>>>(b1, nullptr, n);
    // layer 2
    gemm_scale_kernel<8, true><<<gemm_blocks, 256>>>(nullptr, W2, n);
    agg_kernel<128, true, false><<<agg_blocks, 256>>>(b2, nullptr, n);
    // layer 3
    gemm_scale_kernel<8, true><<<gemm_blocks, 256>>>(nullptr, W3, n);
    agg_kernel<128, true, false><<<agg_blocks, 256>>>(b3, nullptr, n);
    // layer 4 (OUT=64) -> d_out
    gemm_scale_kernel<4, true><<<gemm_blocks, 256>>>(nullptr, W4, n);
    agg_kernel<64, false, true><<<agg_blocks, 256>>>(b4, out, n);
}

// round 9
// speedup vs baseline: 1.1191x; 1.0381x over previous
#include <cuda_runtime.h>
#include <cuda_fp16.h>
#include <cuda_bf16.h>

// Problem constants (GCN_55499567399154)
#define NMAX 50000
#define EMAX 800000
#define FIN  128
#define HID  128
#define NCLS 64

// ---------------- static scratch (no allocations allowed) ----------------
// Device-global symbols are ONLY referenced from device code.
__device__ __align__(256) __half d_bufXh[NMAX * HID]; // activations (fp16)
__device__ __align__(256) __half d_bufG[NMAX * HID];  // g = dinv * (X @ W) (fp16)
__device__ __align__(256) __half d_Wh[3 * 16384 + 8192]; // fp16 weights
__device__ __align__(256) float  d_dinv[NMAX];
__device__ __align__(256) int    d_deg[NMAX];
__device__ __align__(256) int    d_off[NMAX + 8];
__device__ __align__(256) int    d_cur[NMAX];
__device__ __align__(256) int    d_csr[EMAX];
__device__ __align__(256) int    d_bsum[512];
__device__ int d_is64;   // 1 if edge_index is int64, 0 if int32

// ---------------- edge index dtype detection + accessors ----------------
__global__ void detect_kernel(const int* __restrict__ p, int E) {
    if (blockIdx.x == 0 && threadIdx.x == 0) {
        int is64 = 1;
        int cnt = (E < 256) ? E : 256;
        for (int i = 0; i < cnt; i++)
            if (p[2 * i + 1] != 0) { is64 = 0; break; }
        d_is64 = is64;
    }
}
__device__ __forceinline__ int edge_src(const int* p, int E, int e) {
    return d_is64 ? p[2 * e] : p[e];
}
__device__ __forceinline__ int edge_dst(const int* p, int E, int e) {
    return d_is64 ? p[2 * (E + e)] : p[E + e];
}

// ---------------- graph build ----------------
__global__ void deg_init_kernel(int n) {
    int i = blockIdx.x * blockDim.x + threadIdx.x;
    if (i < n) d_deg[i] = 1;  // self-loop
}
__global__ void hist_kernel(const int* __restrict__ ei, int E) {
    int e = blockIdx.x * blockDim.x + threadIdx.x;
    if (e < E) atomicAdd(&d_deg[edge_dst(ei, E, e)], 1);
}
__global__ void scan1_kernel(int n) {
    __shared__ int sh[512];
    int tid = threadIdx.x;
    int i = blockIdx.x * 512 + tid;
    int v = (i < n) ? (d_deg[i] - 1) : 0;
    sh[tid] = v;
    __syncthreads();
#pragma unroll
    for (int dlt = 1; dlt < 512; dlt <<= 1) {
        int t = (tid >= dlt) ? sh[tid - dlt] : 0;
        __syncthreads();
        sh[tid] += t;
        __syncthreads();
    }
    if (i < n) d_off[i] = sh[tid] - v;
    if (tid == 511) d_bsum[blockIdx.x] = sh[511];
}
__global__ void scan2_kernel(int nb, int n) {
    __shared__ int sh[512];
    int tid = threadIdx.x;
    int v = (tid < nb) ? d_bsum[tid] : 0;
    sh[tid] = v;
    __syncthreads();
#pragma unroll
    for (int dlt = 1; dlt < 512; dlt <<= 1) {
        int t = (tid >= dlt) ? sh[tid - dlt] : 0;
        __syncthreads();
        sh[tid] += t;
        __syncthreads();
    }
    if (tid < nb) d_bsum[tid] = sh[tid] - v;
    if (tid == 0) d_off[n] = sh[511];
}
__global__ void scan3_kernel(int n) {
    int i = blockIdx.x * blockDim.x + threadIdx.x;
    if (i < n) {
        int o = d_off[i] + d_bsum[i >> 9];
        d_off[i] = o;
        d_cur[i] = o;
        d_dinv[i] = rsqrtf((float)d_deg[i]);
    }
}
__global__ void fill_kernel(const int* __restrict__ ei, int E) {
    int e = blockIdx.x * blockDim.x + threadIdx.x;
    if (e < E) {
        int c = edge_dst(ei, E, e);
        int p = atomicAdd(&d_cur[c], 1);
        d_csr[p] = edge_src(ei, E, e);
    }
}

// ---------------- fp32 -> fp16 conversions ----------------
__global__ void conv_x_kernel(const float* __restrict__ x, int cnt2) {
    int i = blockIdx.x * blockDim.x + threadIdx.x;  // half2 index
    if (i < cnt2) {
        float2 v = *(const float2*)(x + 2 * i);
        *(__half2*)(d_bufXh + 2 * i) = __floats2half2_rn(v.x, v.y);
    }
}
__global__ void conv_w_kernel(const float* __restrict__ W, int cnt2, int off) {
    int i = blockIdx.x * blockDim.x + threadIdx.x;
    if (i < cnt2) {
        float2 v = *(const float2*)(W + 2 * i);
        *(__half2*)(d_Wh + off + 2 * i) = __floats2half2_rn(v.x, v.y);
    }
}

// ---------------- tensor-core GEMM: G = fp16( dinv .* (Xh @ Wh) ) ----------------
// M-tile 128, N-tile NOUT (<=128), K = 128 in 2 chunks of 64.
// Warp tile 64x32; warps arranged 2 (m) x NOUT/32 (n).
template <int NOUT>
__global__ void __launch_bounds__(64 * (NOUT / 32) * 2 / 2) gemm_tc_kernel(int woff, int n) {
    constexpr int K = 128;
    constexpr int BK = 64;
    constexpr int WN = NOUT / 32;           // warps in n
    constexpr int THREADS = 32 * 2 * WN;    // 2 warps in m
    __shared__ __half Xs[128][BK + 8];      // [m][k]
    __shared__ __half Ws[BK][NOUT + 8];     // [k][n]

    const int tid = threadIdx.x;
    const int lane = tid & 31;
    const int wid = tid >> 5;
    const int wm = wid & 1;          // 0..1
    const int wn = wid >> 1;         // 0..WN-1
    const int row0 = blockIdx.x * 128;
    const int m0 = wm * 64;

    float d[4][4][4];  // [mt][nt][frag]
#pragma unroll
    for (int a = 0; a < 4; a++)
#pragma unroll
        for (int b = 0; b < 4; b++)
#pragma unroll
            for (int c = 0; c < 4; c++) d[a][b][c] = 0.f;

    const __half* Wg = d_Wh + woff;

    for (int kb = 0; kb < K; kb += BK) {
        // load X chunk: 128 x 64 halves = 1024 uint4
#pragma unroll
        for (int it = 0; it < 1024 / THREADS; ++it) {
            int v = tid + it * THREADS;
            int r = v >> 3;
            int kq = v & 7;
            uint4 val = make_uint4(0u, 0u, 0u, 0u);
            int gr = row0 + r;
            if (gr < n)
                val = *(const uint4*)(d_bufXh + (size_t)gr * K + kb + kq * 8);
            *(uint4*)&Xs[r][kq * 8] = val;
        }
        // load W chunk: 64 x NOUT halves = 8*NOUT uint4
#pragma unroll
        for (int it = 0; it < (8 * NOUT) / THREADS; ++it) {
            int v = tid + it * THREADS;
            int k = v / (NOUT / 8);
            int c8 = v % (NOUT / 8);
            *(uint4*)&Ws[k][c8 * 8] =
                *(const uint4*)(Wg + (size_t)(kb + k) * NOUT + c8 * 8);
        }
        __syncthreads();

#pragma unroll
        for (int ks = 0; ks < BK / 16; ++ks) {
            int k0 = ks * 16;
            // A fragments: 4 m16k16 tiles
            unsigned int a[4][4];
#pragma unroll
            for (int mt = 0; mt < 4; mt++) {
                const __half* ap = &Xs[m0 + mt * 16 + (lane & 15)][k0 + ((lane >> 4) << 3)];
                unsigned int addr = (unsigned int)__cvta_generic_to_shared(ap);
                asm volatile(
                    "ldmatrix.sync.aligned.m8n8.x4.shared.b16 {%0,%1,%2,%3}, [%4];\n"
                    : "=r"(a[mt][0]), "=r"(a[mt][1]), "=r"(a[mt][2]), "=r"(a[mt][3])
                    : "r"(addr));
            }
            // B fragments: 4 k16n8 tiles (trans from row-major [k][n])
            unsigned int bb[4][2];
#pragma unroll
            for (int nt = 0; nt < 4; nt++) {
                const __half* bp = &Ws[k0 + (lane & 15)][wn * 32 + nt * 8];
                unsigned int addr = (unsigned int)__cvta_generic_to_shared(bp);
                asm volatile(
                    "ldmatrix.sync.aligned.m8n8.x2.trans.shared.b16 {%0,%1}, [%2];\n"
                    : "=r"(bb[nt][0]), "=r"(bb[nt][1])
                    : "r"(addr));
            }
#pragma unroll
            for (int mt = 0; mt < 4; mt++)
#pragma unroll
                for (int nt = 0; nt < 4; nt++) {
                    asm volatile(
                        "mma.sync.aligned.m16n8k16.row.col.f32.f16.f16.f32 "
                        "{%0,%1,%2,%3}, {%4,%5,%6,%7}, {%8,%9}, {%0,%1,%2,%3};\n"
                        : "+f"(d[mt][nt][0]), "+f"(d[mt][nt][1]),
                          "+f"(d[mt][nt][2]), "+f"(d[mt][nt][3])
                        : "r"(a[mt][0]), "r"(a[mt][1]), "r"(a[mt][2]), "r"(a[mt][3]),
                          "r"(bb[nt][0]), "r"(bb[nt][1]));
                }
        }
        __syncthreads();
    }

    // epilogue: scale by dinv, fp16, store to d_bufG [n][NOUT]
    const int gr = lane >> 2;
    const int tg = lane & 3;
#pragma unroll
    for (int mt = 0; mt < 4; mt++) {
        int r_a = row0 + m0 + mt * 16 + gr;
        int r_b = r_a + 8;
#pragma unroll
        for (int nt = 0; nt < 4; nt++) {
            int col = wn * 32 + nt * 8 + 2 * tg;
            if (r_a < n) {
                float dv = d_dinv[r_a];
                *(__half2*)(d_bufG + (size_t)r_a * NOUT + col) =
                    __floats2half2_rn(d[mt][nt][0] * dv, d[mt][nt][1] * dv);
            }
            if (r_b < n) {
                float dv = d_dinv[r_b];
                *(__half2*)(d_bufG + (size_t)r_b * NOUT + col) =
                    __floats2half2_rn(d[mt][nt][2] * dv, d[mt][nt][3] * dv);
            }
        }
    }
}

// ---------------- aggregation: Y[c] = relu?(dinv[c]*(sum_in g + g[c]) + b) ----------------
// g rows fp16; fp32 accumulate; one warp per node; 4 edges/iter for MLP.
// OUT_PARAM: final layer -> fp32 Yparam; else fp16 d_bufXh.
template <int F, bool RELU, bool OUT_PARAM>
__global__ void __launch_bounds__(256) agg_kernel(
    const float* __restrict__ bias, float* __restrict__ Yparam, int n) {
    constexpr int V = F / 32;  // features per lane (4 or 2)
    int gw = (blockIdx.x * 256 + threadIdx.x) >> 5;
    int lane = threadIdx.x & 31;
    if (gw >= n) return;

    const __half* gbase = d_bufG;

    float acc0 = 0.f, acc1 = 0.f, acc2 = 0.f, acc3 = 0.f;
    {
        const __half* self = gbase + (size_t)gw * F + lane * V;
        if constexpr (V == 4) {
            uint2 rv = *(const uint2*)self;
            float2 f0 = __half22float2(*(const __half2*)&rv.x);
            float2 f1 = __half22float2(*(const __half2*)&rv.y);
            acc0 = f0.x; acc1 = f0.y; acc2 = f1.x; acc3 = f1.y;
        } else {
            unsigned int rv = *(const unsigned int*)self;
            float2 f0 = __half22float2(*(const __half2*)&rv);
            acc0 = f0.x; acc1 = f0.y;
        }
    }

    int s = d_off[gw];
    int e = d_off[gw + 1];
    int j = s;
    for (; j + 3 < e; j += 4) {
        int r0 = d_csr[j];
        int r1 = d_csr[j + 1];
        int r2 = d_csr[j + 2];
        int r3 = d_csr[j + 3];
        if constexpr (V == 4) {
            uint2 v0 = *(const uint2*)(gbase + (size_t)r0 * F + lane * 4);
            uint2 v1 = *(const uint2*)(gbase + (size_t)r1 * F + lane * 4);
            uint2 v2 = *(const uint2*)(gbase + (size_t)r2 * F + lane * 4);
            uint2 v3 = *(const uint2*)(gbase + (size_t)r3 * F + lane * 4);
            float2 a0 = __half22float2(*(const __half2*)&v0.x);
            float2 a1 = __half22float2(*(const __half2*)&v0.y);
            float2 b0 = __half22float2(*(const __half2*)&v1.x);
            float2 b1 = __half22float2(*(const __half2*)&v1.y);
            float2 c0 = __half22float2(*(const __half2*)&v2.x);
            float2 c1 = __half22float2(*(const __half2*)&v2.y);
            float2 e0 = __half22float2(*(const __half2*)&v3.x);
            float2 e1 = __half22float2(*(const __half2*)&v3.y);
            acc0 += (a0.x + b0.x) + (c0.x + e0.x);
            acc1 += (a0.y + b0.y) + (c0.y + e0.y);
            acc2 += (a1.x + b1.x) + (c1.x + e1.x);
            acc3 += (a1.y + b1.y) + (c1.y + e1.y);
        } else {
            unsigned int v0 = *(const unsigned int*)(gbase + (size_t)r0 * F + lane * 2);
            unsigned int v1 = *(const unsigned int*)(gbase + (size_t)r1 * F + lane * 2);
            unsigned int v2 = *(const unsigned int*)(gbase + (size_t)r2 * F + lane * 2);
            unsigned int v3 = *(const unsigned int*)(gbase + (size_t)r3 * F + lane * 2);
            float2 a0 = __half22float2(*(const __half2*)&v0);
            float2 b0 = __half22float2(*(const __half2*)&v1);
            float2 c0 = __half22float2(*(const __half2*)&v2);
            float2 e0 = __half22float2(*(const __half2*)&v3);
            acc0 += (a0.x + b0.x) + (c0.x + e0.x);
            acc1 += (a0.y + b0.y) + (c0.y + e0.y);
        }
    }
    for (; j < e; j++) {
        int r0 = d_csr[j];
        if constexpr (V == 4) {
            uint2 v0 = *(const uint2*)(gbase + (size_t)r0 * F + lane * 4);
            float2 a0 = __half22float2(*(const __half2*)&v0.x);
            float2 a1 = __half22float2(*(const __half2*)&v0.y);
            acc0 += a0.x; acc1 += a0.y; acc2 += a1.x; acc3 += a1.y;
        } else {
            unsigned int v0 = *(const unsigned int*)(gbase + (size_t)r0 * F + lane * 2);
            float2 a0 = __half22float2(*(const __half2*)&v0);
            acc0 += a0.x; acc1 += a0.y;
        }
    }

    float dv = d_dinv[gw];
    if constexpr (V == 4) {
        float4 bv = *(const float4*)(bias + lane * 4);
        float o0 = dv * acc0 + bv.x;
        float o1 = dv * acc1 + bv.y;
        float o2 = dv * acc2 + bv.z;
        float o3 = dv * acc3 + bv.w;
        if (RELU) {
            o0 = fmaxf(o0, 0.f); o1 = fmaxf(o1, 0.f);
            o2 = fmaxf(o2, 0.f); o3 = fmaxf(o3, 0.f);
        }
        if constexpr (OUT_PARAM) {
            *(float4*)(Yparam + (size_t)gw * F + lane * 4) =
                make_float4(o0, o1, o2, o3);
        } else {
            uint2 hv;
            __half2 h0 = __floats2half2_rn(o0, o1);
            __half2 h1 = __floats2half2_rn(o2, o3);
            hv.x = *(unsigned int*)&h0;
            hv.y = *(unsigned int*)&h1;
            *(uint2*)(d_bufXh + (size_t)gw * F + lane * 4) = hv;
        }
    } else {
        float2 bv = *(const float2*)(bias + lane * 2);
        float o0 = dv * acc0 + bv.x;
        float o1 = dv * acc1 + bv.y;
        if (RELU) { o0 = fmaxf(o0, 0.f); o1 = fmaxf(o1, 0.f); }
        if constexpr (OUT_PARAM) {
            *(float2*)(Yparam + (size_t)gw * F + lane * 2) = make_float2(o0, o1);
        } else {
            __half2 h0 = __floats2half2_rn(o0, o1);
            *(unsigned int*)(d_bufXh + (size_t)gw * F + lane * 2) =
                *(unsigned int*)&h0;
        }
    }
}

// ---------------- launch ----------------
extern "C" void kernel_launch(void* const* d_in, const int* in_sizes, int n_in,
                              void* d_out, int out_size) {
    const float* x  = (const float*)d_in[0];
    const int*   ei = (const int*)d_in[1];   // int32 or int64 words; auto-detected
    const float* W1 = (const float*)d_in[2];
    const float* b1 = (const float*)d_in[3];
    const float* W2 = (const float*)d_in[4];
    const float* b2 = (const float*)d_in[5];
    const float* W3 = (const float*)d_in[6];
    const float* b3 = (const float*)d_in[7];
    const float* W4 = (const float*)d_in[8];
    const float* b4 = (const float*)d_in[9];
    float* out = (float*)d_out;

    int n = in_sizes[0] / FIN;
    int E = in_sizes[1] / 2;

    // graph build
    detect_kernel<<<1, 32>>>(ei, E);
    deg_init_kernel<<<(n + 255) / 256, 256>>>(n);
    hist_kernel<<<(E + 255) / 256, 256>>>(ei, E);
    int nb = (n + 511) / 512;
    scan1_kernel<<<nb, 512>>>(n);
    scan2_kernel<<<1, 512>>>(nb, n);
    scan3_kernel<<<(n + 255) / 256, 256>>>(n);
    fill_kernel<<<(E + 255) / 256, 256>>>(ei, E);

    // conversions
    int xc2 = n * FIN / 2;
    conv_x_kernel<<<(xc2 + 255) / 256, 256>>>(x, xc2);
    conv_w_kernel<<<(8192 + 255) / 256, 256>>>(W1, 8192, 0);
    conv_w_kernel<<<(8192 + 255) / 256, 256>>>(W2, 8192, 16384);
    conv_w_kernel<<<(8192 + 255) / 256, 256>>>(W3, 8192, 32768);
    conv_w_kernel<<<(4096 + 255) / 256, 256>>>(W4, 4096, 49152);

    int gemm_blocks = (n + 127) / 128;
    int agg_blocks = (n * 32 + 255) / 256;

    // layer 1
    gemm_tc_kernel<128><<<gemm_blocks, 256>>>(0, n);
    agg_kernel<128, true, false><<<agg_blocks, 256>>>(b1, nullptr, n);
    // layer 2
    gemm_tc_kernel<128><<<gemm_blocks, 256>>>(16384, n);
    agg_kernel<128, true, false><<<agg_blocks, 256>>>(b2, nullptr, n);
    // layer 3
    gemm_tc_kernel<128><<<gemm_blocks, 256>>>(32768, n);
    agg_kernel<128, true, false><<<agg_blocks, 256>>>(b3, nullptr, n);
    // layer 4 (OUT=64) -> d_out
    gemm_tc_kernel<64><<<gemm_blocks, 128>>>(49152, n);
    agg_kernel<64, false, true><<<agg_blocks, 256>>>(b4, out, n);
}

// round 10
// speedup vs baseline: 1.6171x; 1.4449x over previous
#include <cuda_runtime.h>
#include <cuda_fp16.h>
#include <cuda_bf16.h>

// Problem constants (GCN_55499567399154)
#define NMAX 50000
#define EMAX 800000
#define FIN  128
#define HID  128
#define NCLS 64

// ---------------- static scratch (no allocations allowed) ----------------
// Device-global symbols are ONLY referenced from device code.
__device__ __align__(256) __half d_bufXh[NMAX * HID]; // activations (fp16)
__device__ __align__(256) __half d_bufG[NMAX * HID];  // g = dinv * (X @ W) (fp16)
__device__ __align__(256) __half d_Wh[3 * 16384 + 8192]; // fp16 weights
__device__ __align__(256) float  d_dinv[NMAX];
__device__ __align__(256) int    d_deg[NMAX];
__device__ __align__(256) int    d_off[NMAX + 8];
__device__ __align__(256) int    d_cur[NMAX];
__device__ __align__(256) int    d_csr[EMAX];
__device__ __align__(256) int    d_bsum[512];
__device__ int d_is64;   // 1 if edge_index is int64, 0 if int32

// ---------------- edge index dtype detection + accessors ----------------
__global__ void detect_kernel(const int* __restrict__ p, int E) {
    if (blockIdx.x == 0 && threadIdx.x == 0) {
        int is64 = 1;
        int cnt = (E < 256) ? E : 256;
        for (int i = 0; i < cnt; i++)
            if (p[2 * i + 1] != 0) { is64 = 0; break; }
        d_is64 = is64;
    }
}
__device__ __forceinline__ int edge_src(const int* p, int E, int e) {
    return d_is64 ? p[2 * e] : p[e];
}
__device__ __forceinline__ int edge_dst(const int* p, int E, int e) {
    return d_is64 ? p[2 * (E + e)] : p[E + e];
}

// ---------------- graph build ----------------
__global__ void deg_init_kernel(int n) {
    int i = blockIdx.x * blockDim.x + threadIdx.x;
    if (i < n) d_deg[i] = 1;  // self-loop
}
__global__ void hist_kernel(const int* __restrict__ ei, int E) {
    int e = blockIdx.x * blockDim.x + threadIdx.x;
    if (e < E) atomicAdd(&d_deg[edge_dst(ei, E, e)], 1);
}
__global__ void scan1_kernel(int n) {
    __shared__ int sh[512];
    int tid = threadIdx.x;
    int i = blockIdx.x * 512 + tid;
    int v = (i < n) ? (d_deg[i] - 1) : 0;
    sh[tid] = v;
    __syncthreads();
#pragma unroll
    for (int dlt = 1; dlt < 512; dlt <<= 1) {
        int t = (tid >= dlt) ? sh[tid - dlt] : 0;
        __syncthreads();
        sh[tid] += t;
        __syncthreads();
    }
    if (i < n) d_off[i] = sh[tid] - v;
    if (tid == 511) d_bsum[blockIdx.x] = sh[511];
}
__global__ void scan2_kernel(int nb, int n) {
    __shared__ int sh[512];
    int tid = threadIdx.x;
    int v = (tid < nb) ? d_bsum[tid] : 0;
    sh[tid] = v;
    __syncthreads();
#pragma unroll
    for (int dlt = 1; dlt < 512; dlt <<= 1) {
        int t = (tid >= dlt) ? sh[tid - dlt] : 0;
        __syncthreads();
        sh[tid] += t;
        __syncthreads();
    }
    if (tid < nb) d_bsum[tid] = sh[tid] - v;
    if (tid == 0) d_off[n] = sh[511];
}
__global__ void scan3_kernel(int n) {
    int i = blockIdx.x * blockDim.x + threadIdx.x;
    if (i < n) {
        int o = d_off[i] + d_bsum[i >> 9];
        d_off[i] = o;
        d_cur[i] = o;
        d_dinv[i] = rsqrtf((float)d_deg[i]);
    }
}
__global__ void fill_kernel(const int* __restrict__ ei, int E) {
    int e = blockIdx.x * blockDim.x + threadIdx.x;
    if (e < E) {
        int c = edge_dst(ei, E, e);
        int p = atomicAdd(&d_cur[c], 1);
        d_csr[p] = edge_src(ei, E, e);
    }
}

// ---------------- fp32 -> fp16 conversions ----------------
__global__ void conv_x_kernel(const float* __restrict__ x, int cnt2) {
    int i = blockIdx.x * blockDim.x + threadIdx.x;  // half2 index
    if (i < cnt2) {
        float2 v = *(const float2*)(x + 2 * i);
        *(__half2*)(d_bufXh + 2 * i) = __floats2half2_rn(v.x, v.y);
    }
}
__global__ void conv_w_kernel(const float* __restrict__ W, int cnt2, int off) {
    int i = blockIdx.x * blockDim.x + threadIdx.x;
    if (i < cnt2) {
        float2 v = *(const float2*)(W + 2 * i);
        *(__half2*)(d_Wh + off + 2 * i) = __floats2half2_rn(v.x, v.y);
    }
}

// ---------------- tensor-core GEMM: G = fp16( dinv .* (Xh @ Wh) ) ----------------
// M-tile 128, N-tile NOUT (<=128), K = 128 in 2 chunks of 64.
// Warp tile 64x32; warps arranged 2 (m) x NOUT/32 (n).
template <int NOUT>
__global__ void __launch_bounds__(64 * (NOUT / 32) * 2 / 2) gemm_tc_kernel(int woff, int n) {
    constexpr int K = 128;
    constexpr int BK = 64;
    constexpr int WN = NOUT / 32;           // warps in n
    constexpr int THREADS = 32 * 2 * WN;    // 2 warps in m
    __shared__ __half Xs[128][BK + 8];      // [m][k]
    __shared__ __half Ws[BK][NOUT + 8];     // [k][n]

    const int tid = threadIdx.x;
    const int lane = tid & 31;
    const int wid = tid >> 5;
    const int wm = wid & 1;          // 0..1
    const int wn = wid >> 1;         // 0..WN-1
    const int row0 = blockIdx.x * 128;
    const int m0 = wm * 64;

    float d[4][4][4];  // [mt][nt][frag]
#pragma unroll
    for (int a = 0; a < 4; a++)
#pragma unroll
        for (int b = 0; b < 4; b++)
#pragma unroll
            for (int c = 0; c < 4; c++) d[a][b][c] = 0.f;

    const __half* Wg = d_Wh + woff;

    for (int kb = 0; kb < K; kb += BK) {
        // load X chunk: 128 x 64 halves = 1024 uint4
#pragma unroll
        for (int it = 0; it < 1024 / THREADS; ++it) {
            int v = tid + it * THREADS;
            int r = v >> 3;
            int kq = v & 7;
            uint4 val = make_uint4(0u, 0u, 0u, 0u);
            int gr = row0 + r;
            if (gr < n)
                val = *(const uint4*)(d_bufXh + (size_t)gr * K + kb + kq * 8);
            *(uint4*)&Xs[r][kq * 8] = val;
        }
        // load W chunk: 64 x NOUT halves = 8*NOUT uint4
#pragma unroll
        for (int it = 0; it < (8 * NOUT) / THREADS; ++it) {
            int v = tid + it * THREADS;
            int k = v / (NOUT / 8);
            int c8 = v % (NOUT / 8);
            *(uint4*)&Ws[k][c8 * 8] =
                *(const uint4*)(Wg + (size_t)(kb + k) * NOUT + c8 * 8);
        }
        __syncthreads();

#pragma unroll
        for (int ks = 0; ks < BK / 16; ++ks) {
            int k0 = ks * 16;
            // A fragments: 4 m16k16 tiles
            unsigned int a[4][4];
#pragma unroll
            for (int mt = 0; mt < 4; mt++) {
                const __half* ap = &Xs[m0 + mt * 16 + (lane & 15)][k0 + ((lane >> 4) << 3)];
                unsigned int addr = (unsigned int)__cvta_generic_to_shared(ap);
                asm volatile(
                    "ldmatrix.sync.aligned.m8n8.x4.shared.b16 {%0,%1,%2,%3}, [%4];\n"
                    : "=r"(a[mt][0]), "=r"(a[mt][1]), "=r"(a[mt][2]), "=r"(a[mt][3])
                    : "r"(addr));
            }
            // B fragments: 4 k16n8 tiles (trans from row-major [k][n])
            unsigned int bb[4][2];
#pragma unroll
            for (int nt = 0; nt < 4; nt++) {
                const __half* bp = &Ws[k0 + (lane & 15)][wn * 32 + nt * 8];
                unsigned int addr = (unsigned int)__cvta_generic_to_shared(bp);
                asm volatile(
                    "ldmatrix.sync.aligned.m8n8.x2.trans.shared.b16 {%0,%1}, [%2];\n"
                    : "=r"(bb[nt][0]), "=r"(bb[nt][1])
                    : "r"(addr));
            }
#pragma unroll
            for (int mt = 0; mt < 4; mt++)
#pragma unroll
                for (int nt = 0; nt < 4; nt++) {
                    asm volatile(
                        "mma.sync.aligned.m16n8k16.row.col.f32.f16.f16.f32 "
                        "{%0,%1,%2,%3}, {%4,%5,%6,%7}, {%8,%9}, {%0,%1,%2,%3};\n"
                        : "+f"(d[mt][nt][0]), "+f"(d[mt][nt][1]),
                          "+f"(d[mt][nt][2]), "+f"(d[mt][nt][3])
                        : "r"(a[mt][0]), "r"(a[mt][1]), "r"(a[mt][2]), "r"(a[mt][3]),
                          "r"(bb[nt][0]), "r"(bb[nt][1]));
                }
        }
        __syncthreads();
    }

    // epilogue: scale by dinv, fp16, store to d_bufG [n][NOUT]
    const int gr = lane >> 2;
    const int tg = lane & 3;
#pragma unroll
    for (int mt = 0; mt < 4; mt++) {
        int r_a = row0 + m0 + mt * 16 + gr;
        int r_b = r_a + 8;
#pragma unroll
        for (int nt = 0; nt < 4; nt++) {
            int col = wn * 32 + nt * 8 + 2 * tg;
            if (r_a < n) {
                float dv = d_dinv[r_a];
                *(__half2*)(d_bufG + (size_t)r_a * NOUT + col) =
                    __floats2half2_rn(d[mt][nt][0] * dv, d[mt][nt][1] * dv);
            }
            if (r_b < n) {
                float dv = d_dinv[r_b];
                *(__half2*)(d_bufG + (size_t)r_b * NOUT + col) =
                    __floats2half2_rn(d[mt][nt][2] * dv, d[mt][nt][3] * dv);
            }
        }
    }
}

// ---------------- aggregation: Y[c] = relu?(dinv[c]*(sum_in g + g[c]) + b) ----------------
// g rows fp16; fp32 accumulate; one warp per node.
// Latency-chain fix: 32 edge indices fetched per COALESCED csr load (lane-
// distributed), read back via shfl; gathers batched 8-deep for MLP.
// OUT_PARAM: final layer -> fp32 Yparam; else fp16 d_bufXh.
template <int F, bool RELU, bool OUT_PARAM>
__global__ void __launch_bounds__(256) agg_kernel(
    const float* __restrict__ bias, float* __restrict__ Yparam, int n) {
    constexpr int V = F / 32;  // features per lane (4 or 2)
    int gw = (blockIdx.x * 256 + threadIdx.x) >> 5;
    int lane = threadIdx.x & 31;
    if (gw >= n) return;

    const __half* gbase = d_bufG;

    float acc0 = 0.f, acc1 = 0.f, acc2 = 0.f, acc3 = 0.f;

    // helper lambdas for one gathered row
    auto addrow4 = [&](int r, float& a0, float& a1, float& a2, float& a3) {
        uint2 v = *(const uint2*)(gbase + (size_t)r * F + lane * 4);
        float2 f0 = __half22float2(*(const __half2*)&v.x);
        float2 f1 = __half22float2(*(const __half2*)&v.y);
        a0 += f0.x; a1 += f0.y; a2 += f1.x; a3 += f1.y;
    };
    auto addrow2 = [&](int r, float& a0, float& a1) {
        unsigned int v = *(const unsigned int*)(gbase + (size_t)r * F + lane * 2);
        float2 f0 = __half22float2(*(const __half2*)&v);
        a0 += f0.x; a1 += f0.y;
    };

    // self contribution
    if constexpr (V == 4) addrow4(gw, acc0, acc1, acc2, acc3);
    else                  addrow2(gw, acc0, acc1);

    int s = d_off[gw];
    int e = d_off[gw + 1];

    for (int base = s; base < e; base += 32) {
        int cnt = e - base;
        if (cnt > 32) cnt = 32;
        int idx = 0;
        if (lane < cnt) idx = d_csr[base + lane];  // coalesced: 32 indices/1 load

        int k = 0;
        for (; k + 7 < cnt; k += 8) {
            int r[8];
#pragma unroll
            for (int i = 0; i < 8; i++)
                r[i] = __shfl_sync(0xffffffffu, idx, k + i);
            if constexpr (V == 4) {
                uint2 v[8];
#pragma unroll
                for (int i = 0; i < 8; i++)
                    v[i] = *(const uint2*)(gbase + (size_t)r[i] * F + lane * 4);
#pragma unroll
                for (int i = 0; i < 8; i++) {
                    float2 f0 = __half22float2(*(const __half2*)&v[i].x);
                    float2 f1 = __half22float2(*(const __half2*)&v[i].y);
                    acc0 += f0.x; acc1 += f0.y; acc2 += f1.x; acc3 += f1.y;
                }
            } else {
                unsigned int v[8];
#pragma unroll
                for (int i = 0; i < 8; i++)
                    v[i] = *(const unsigned int*)(gbase + (size_t)r[i] * F + lane * 2);
#pragma unroll
                for (int i = 0; i < 8; i++) {
                    float2 f0 = __half22float2(*(const __half2*)&v[i]);
                    acc0 += f0.x; acc1 += f0.y;
                }
            }
        }
        for (; k + 3 < cnt; k += 4) {
            int r[4];
#pragma unroll
            for (int i = 0; i < 4; i++)
                r[i] = __shfl_sync(0xffffffffu, idx, k + i);
            if constexpr (V == 4) {
                uint2 v[4];
#pragma unroll
                for (int i = 0; i < 4; i++)
                    v[i] = *(const uint2*)(gbase + (size_t)r[i] * F + lane * 4);
#pragma unroll
                for (int i = 0; i < 4; i++) {
                    float2 f0 = __half22float2(*(const __half2*)&v[i].x);
                    float2 f1 = __half22float2(*(const __half2*)&v[i].y);
                    acc0 += f0.x; acc1 += f0.y; acc2 += f1.x; acc3 += f1.y;
                }
            } else {
                unsigned int v[4];
#pragma unroll
                for (int i = 0; i < 4; i++)
                    v[i] = *(const unsigned int*)(gbase + (size_t)r[i] * F + lane * 2);
#pragma unroll
                for (int i = 0; i < 4; i++) {
                    float2 f0 = __half22float2(*(const __half2*)&v[i]);
                    acc0 += f0.x; acc1 += f0.y;
                }
            }
        }
        for (; k < cnt; k++) {
            int r = __shfl_sync(0xffffffffu, idx, k);
            if constexpr (V == 4) addrow4(r, acc0, acc1, acc2, acc3);
            else                  addrow2(r, acc0, acc1);
        }
    }

    float dv = d_dinv[gw];
    if constexpr (V == 4) {
        float4 bv = *(const float4*)(bias + lane * 4);
        float o0 = dv * acc0 + bv.x;
        float o1 = dv * acc1 + bv.y;
        float o2 = dv * acc2 + bv.z;
        float o3 = dv * acc3 + bv.w;
        if (RELU) {
            o0 = fmaxf(o0, 0.f); o1 = fmaxf(o1, 0.f);
            o2 = fmaxf(o2, 0.f); o3 = fmaxf(o3, 0.f);
        }
        if constexpr (OUT_PARAM) {
            *(float4*)(Yparam + (size_t)gw * F + lane * 4) =
                make_float4(o0, o1, o2, o3);
        } else {
            uint2 hv;
            __half2 h0 = __floats2half2_rn(o0, o1);
            __half2 h1 = __floats2half2_rn(o2, o3);
            hv.x = *(unsigned int*)&h0;
            hv.y = *(unsigned int*)&h1;
            *(uint2*)(d_bufXh + (size_t)gw * F + lane * 4) = hv;
        }
    } else {
        float2 bv = *(const float2*)(bias + lane * 2);
        float o0 = dv * acc0 + bv.x;
        float o1 = dv * acc1 + bv.y;
        if (RELU) { o0 = fmaxf(o0, 0.f); o1 = fmaxf(o1, 0.f); }
        if constexpr (OUT_PARAM) {
            *(float2*)(Yparam + (size_t)gw * F + lane * 2) = make_float2(o0, o1);
        } else {
            __half2 h0 = __floats2half2_rn(o0, o1);
            *(unsigned int*)(d_bufXh + (size_t)gw * F + lane * 2) =
                *(unsigned int*)&h0;
        }
    }
}

// ---------------- launch ----------------
extern "C" void kernel_launch(void* const* d_in, const int* in_sizes, int n_in,
                              void* d_out, int out_size) {
    const float* x  = (const float*)d_in[0];
    const int*   ei = (const int*)d_in[1];   // int32 or int64 words; auto-detected
    const float* W1 = (const float*)d_in[2];
    const float* b1 = (const float*)d_in[3];
    const float* W2 = (const float*)d_in[4];
    const float* b2 = (const float*)d_in[5];
    const float* W3 = (const float*)d_in[6];
    const float* b3 = (const float*)d_in[7];
    const float* W4 = (const float*)d_in[8];
    const float* b4 = (const float*)d_in[9];
    float* out = (float*)d_out;

    int n = in_sizes[0] / FIN;
    int E = in_sizes[1] / 2;

    // graph build
    detect_kernel<<<1, 32>>>(ei, E);
    deg_init_kernel<<<(n + 255) / 256, 256>>>(n);
    hist_kernel<<<(E + 255) / 256, 256>>>(ei, E);
    int nb = (n + 511) / 512;
    scan1_kernel<<<nb, 512>>>(n);
    scan2_kernel<<<1, 512>>>(nb, n);
    scan3_kernel<<<(n + 255) / 256, 256>>>(n);
    fill_kernel<<<(E + 255) / 256, 256>>>(ei, E);

    // conversions
    int xc2 = n * FIN / 2;
    conv_x_kernel<<<(xc2 + 255) / 256, 256>>>(x, xc2);
    conv_w_kernel<<<(8192 + 255) / 256, 256>>>(W1, 8192, 0);
    conv_w_kernel<<<(8192 + 255) / 256, 256>>>(W2, 8192, 16384);
    conv_w_kernel<<<(8192 + 255) / 256, 256>>>(W3, 8192, 32768);
    conv_w_kernel<<<(4096 + 255) / 256, 256>>>(W4, 4096, 49152);

    int gemm_blocks = (n + 127) / 128;
    int agg_blocks = (n * 32 + 255) / 256;

    // layer 1
    gemm_tc_kernel<128><<<gemm_blocks, 256>>>(0, n);
    agg_kernel<128, true, false><<<agg_blocks, 256>>>(b1, nullptr, n);
    // layer 2
    gemm_tc_kernel<128><<<gemm_blocks, 256>>>(16384, n);
    agg_kernel<128, true, false><<<agg_blocks, 256>>>(b2, nullptr, n);
    // layer 3
    gemm_tc_kernel<128><<<gemm_blocks, 256>>>(32768, n);
    agg_kernel<128, true, false><<<agg_blocks, 256>>>(b3, nullptr, n);
    // layer 4 (OUT=64) -> d_out
    gemm_tc_kernel<64><<<gemm_blocks, 128>>>(49152, n);
    agg_kernel<64, false, true><<<agg_blocks, 256>>>(b4, out, n);
}

// round 12
// speedup vs baseline: 1.6334x; 1.0101x over previous
#include <cuda_runtime.h>
#include <cuda_fp16.h>
#include <cuda_bf16.h>

// Problem constants (GCN_55499567399154)
#define NMAX 50000
#define EMAX 800000
#define FIN  128
#define HID  128
#define NCLS 64

// ---------------- static scratch (no allocations allowed) ----------------
__device__ __align__(256) __half d_bufXh[NMAX * HID]; // activations (fp16)
__device__ __align__(256) __half d_bufG[NMAX * HID];  // g = dinv * (X @ W) (fp16)
__device__ __align__(256) __half d_Wh[3 * 16384 + 8192]; // fp16 weights
__device__ __align__(256) float  d_dinv[NMAX];
__device__ __align__(256) int    d_deg[NMAX];
__device__ __align__(256) int    d_off[NMAX + 8];
__device__ __align__(256) int    d_cur[NMAX];
__device__ __align__(256) int    d_csr[EMAX];
__device__ __align__(256) int    d_bsum[512];
__device__ int d_is64;   // 1 if edge_index is int64, 0 if int32

template <int N> struct Int { static constexpr int value = N; };

// ---------------- edge index accessors ----------------
__device__ __forceinline__ int edge_src(const int* p, int E, int e) {
    return d_is64 ? p[2 * e] : p[e];
}
__device__ __forceinline__ int edge_dst(const int* p, int E, int e) {
    return d_is64 ? p[2 * (E + e)] : p[E + e];
}

// ---------------- graph build ----------------
// deg init + PARALLEL dtype detect (256 threads check odd words, not 1 serial thread)
__global__ void init_kernel(const int* __restrict__ p, int E, int n) {
    int i = blockIdx.x * blockDim.x + threadIdx.x;
    if (i < n) d_deg[i] = 1;  // self-loop
    if (blockIdx.x == 0) {
        __shared__ int bad;
        if (threadIdx.x == 0) bad = 0;
        __syncthreads();
        int cnt = (E < 256) ? E : 256;
        if ((int)threadIdx.x < cnt && p[2 * threadIdx.x + 1] != 0) bad = 1;
        __syncthreads();
        if (threadIdx.x == 0) d_is64 = bad ? 0 : 1;
    }
}
__global__ void hist_kernel(const int* __restrict__ ei, int E) {
    int e = blockIdx.x * blockDim.x + threadIdx.x;
    if (e < E) atomicAdd(&d_deg[edge_dst(ei, E, e)], 1);
}
__global__ void scan1_kernel(int n) {
    __shared__ int sh[512];
    int tid = threadIdx.x;
    int i = blockIdx.x * 512 + tid;
    int v = (i < n) ? (d_deg[i] - 1) : 0;
    sh[tid] = v;
    __syncthreads();
#pragma unroll
    for (int dlt = 1; dlt < 512; dlt <<= 1) {
        int t = (tid >= dlt) ? sh[tid - dlt] : 0;
        __syncthreads();
        sh[tid] += t;
        __syncthreads();
    }
    if (i < n) d_off[i] = sh[tid] - v;
    if (tid == 511) d_bsum[blockIdx.x] = sh[511];
}
__global__ void scan2_kernel(int nb, int n) {
    __shared__ int sh[512];
    int tid = threadIdx.x;
    int v = (tid < nb) ? d_bsum[tid] : 0;
    sh[tid] = v;
    __syncthreads();
#pragma unroll
    for (int dlt = 1; dlt < 512; dlt <<= 1) {
        int t = (tid >= dlt) ? sh[tid - dlt] : 0;
        __syncthreads();
        sh[tid] += t;
        __syncthreads();
    }
    if (tid < nb) d_bsum[tid] = sh[tid] - v;
    if (tid == 0) d_off[n] = sh[511];
}
__global__ void scan3_kernel(int n) {
    int i = blockIdx.x * blockDim.x + threadIdx.x;
    if (i < n) {
        int o = d_off[i] + d_bsum[i >> 9];
        d_off[i] = o;
        d_cur[i] = o;
        d_dinv[i] = rsqrtf((float)d_deg[i]);
    }
}
__global__ void fill_kernel(const int* __restrict__ ei, int E) {
    int e = blockIdx.x * blockDim.x + threadIdx.x;
    if (e < E) {
        int c = edge_dst(ei, E, e);
        int p = atomicAdd(&d_cur[c], 1);
        d_csr[p] = edge_src(ei, E, e);
    }
}

// ---------------- fp32 -> fp16 conversions ----------------
__global__ void conv_x_kernel(const float* __restrict__ x, int cnt2) {
    int i = blockIdx.x * blockDim.x + threadIdx.x;  // half2 index
    if (i < cnt2) {
        float2 v = *(const float2*)(x + 2 * i);
        *(__half2*)(d_bufXh + 2 * i) = __floats2half2_rn(v.x, v.y);
    }
}
// all 4 weight matrices in ONE launch; d_Wh layout: W1[0,16384) W2[16384,32768) W3[32768,49152) W4[49152,57344)
__global__ void conv_w_all_kernel(const float* __restrict__ W1, const float* __restrict__ W2,
                                  const float* __restrict__ W3, const float* __restrict__ W4) {
    int i = blockIdx.x * blockDim.x + threadIdx.x;  // half2 index, 28672 total
    if (i >= 28672) return;
    const float* src;
    if (i < 8192)       src = W1 + 2 * i;
    else if (i < 16384) src = W2 + 2 * i - 16384;
    else if (i < 24576) src = W3 + 2 * i - 32768;
    else                src = W4 + 2 * i - 49152;
    float2 v = *(const float2*)src;
    *(__half2*)(d_Wh + 2 * i) = __floats2half2_rn(v.x, v.y);
}

// ---------------- tensor-core GEMM: G = fp16( dinv .* (Xh @ Wh) ) ----------------
template <int NOUT>
__global__ void __launch_bounds__(64 * (NOUT / 32) * 2 / 2) gemm_tc_kernel(int woff, int n) {
    constexpr int K = 128;
    constexpr int BK = 64;
    constexpr int WN = NOUT / 32;
    constexpr int THREADS = 32 * 2 * WN;
    __shared__ __half Xs[128][BK + 8];
    __shared__ __half Ws[BK][NOUT + 8];

    const int tid = threadIdx.x;
    const int lane = tid & 31;
    const int wid = tid >> 5;
    const int wm = wid & 1;
    const int wn = wid >> 1;
    const int row0 = blockIdx.x * 128;
    const int m0 = wm * 64;

    float d[4][4][4];
#pragma unroll
    for (int a = 0; a < 4; a++)
#pragma unroll
        for (int b = 0; b < 4; b++)
#pragma unroll
            for (int c = 0; c < 4; c++) d[a][b][c] = 0.f;

    const __half* Wg = d_Wh + woff;

    for (int kb = 0; kb < K; kb += BK) {
#pragma unroll
        for (int it = 0; it < 1024 / THREADS; ++it) {
            int v = tid + it * THREADS;
            int r = v >> 3;
            int kq = v & 7;
            uint4 val = make_uint4(0u, 0u, 0u, 0u);
            int gr = row0 + r;
            if (gr < n)
                val = *(const uint4*)(d_bufXh + (size_t)gr * K + kb + kq * 8);
            *(uint4*)&Xs[r][kq * 8] = val;
        }
#pragma unroll
        for (int it = 0; it < (8 * NOUT) / THREADS; ++it) {
            int v = tid + it * THREADS;
            int k = v / (NOUT / 8);
            int c8 = v % (NOUT / 8);
            *(uint4*)&Ws[k][c8 * 8] =
                *(const uint4*)(Wg + (size_t)(kb + k) * NOUT + c8 * 8);
        }
        __syncthreads();

#pragma unroll
        for (int ks = 0; ks < BK / 16; ++ks) {
            int k0 = ks * 16;
            unsigned int a[4][4];
#pragma unroll
            for (int mt = 0; mt < 4; mt++) {
                const __half* ap = &Xs[m0 + mt * 16 + (lane & 15)][k0 + ((lane >> 4) << 3)];
                unsigned int addr = (unsigned int)__cvta_generic_to_shared(ap);
                asm volatile(
                    "ldmatrix.sync.aligned.m8n8.x4.shared.b16 {%0,%1,%2,%3}, [%4];\n"
                    : "=r"(a[mt][0]), "=r"(a[mt][1]), "=r"(a[mt][2]), "=r"(a[mt][3])
                    : "r"(addr));
            }
            unsigned int bb[4][2];
#pragma unroll
            for (int nt = 0; nt < 4; nt++) {
                const __half* bp = &Ws[k0 + (lane & 15)][wn * 32 + nt * 8];
                unsigned int addr = (unsigned int)__cvta_generic_to_shared(bp);
                asm volatile(
                    "ldmatrix.sync.aligned.m8n8.x2.trans.shared.b16 {%0,%1}, [%2];\n"
                    : "=r"(bb[nt][0]), "=r"(bb[nt][1])
                    : "r"(addr));
            }
#pragma unroll
            for (int mt = 0; mt < 4; mt++)
#pragma unroll
                for (int nt = 0; nt < 4; nt++) {
                    asm volatile(
                        "mma.sync.aligned.m16n8k16.row.col.f32.f16.f16.f32 "
                        "{%0,%1,%2,%3}, {%4,%5,%6,%7}, {%8,%9}, {%0,%1,%2,%3};\n"
                        : "+f"(d[mt][nt][0]), "+f"(d[mt][nt][1]),
                          "+f"(d[mt][nt][2]), "+f"(d[mt][nt][3])
                        : "r"(a[mt][0]), "r"(a[mt][1]), "r"(a[mt][2]), "r"(a[mt][3]),
                          "r"(bb[nt][0]), "r"(bb[nt][1]));
                }
        }
        __syncthreads();
    }

    const int gr = lane >> 2;
    const int tg = lane & 3;
#pragma unroll
    for (int mt = 0; mt < 4; mt++) {
        int r_a = row0 + m0 + mt * 16 + gr;
        int r_b = r_a + 8;
#pragma unroll
        for (int nt = 0; nt < 4; nt++) {
            int col = wn * 32 + nt * 8 + 2 * tg;
            if (r_a < n) {
                float dv = d_dinv[r_a];
                *(__half2*)(d_bufG + (size_t)r_a * NOUT + col) =
                    __floats2half2_rn(d[mt][nt][0] * dv, d[mt][nt][1] * dv);
            }
            if (r_b < n) {
                float dv = d_dinv[r_b];
                *(__half2*)(d_bufG + (size_t)r_b * NOUT + col) =
                    __floats2half2_rn(d[mt][nt][2] * dv, d[mt][nt][3] * dv);
            }
        }
    }
}

// ---------------- aggregation: Y[c] = relu?(dinv[c]*(sum_in g + g[c]) + b) ----------------
// Pair-gather: warp splits into two 16-lane halves; each lane loads C=F/16
// features (uint4/uint2), lower half gathers even edges, upper half odd edges
// IN THE SAME instruction -> 8 outstanding loads cover 16 edges. Halves merge
// via one shfl_xor(16) per accumulator at the end.
template <int F, bool RELU, bool OUT_PARAM>
__global__ void __launch_bounds__(256) agg_kernel(
    const float* __restrict__ bias, float* __restrict__ Yparam, int n) {
    constexpr int C = F / 16;  // features per lane (8 or 4)
    int gw = (blockIdx.x * 256 + threadIdx.x) >> 5;
    int lane = threadIdx.x & 31;
    int hf = lane >> 4;        // 0 = even edges, 1 = odd edges
    int hl = lane & 15;        // position within half-warp
    if (gw >= n) return;

    const __half* gbase = d_bufG;
    float acc[C];
#pragma unroll
    for (int i = 0; i < C; i++) acc[i] = 0.f;

    auto addv = [&](const unsigned int* w) {
#pragma unroll
        for (int j = 0; j < C / 2; j++) {
            float2 f = __half22float2(*(const __half2*)&w[j]);
            acc[2 * j] += f.x;
            acc[2 * j + 1] += f.y;
        }
    };
    auto loadrow = [&](int r) {
        if constexpr (C == 8) {
            uint4 v = *(const uint4*)(gbase + (size_t)r * F + hl * 8);
            addv((const unsigned int*)&v);
        } else {
            uint2 v = *(const uint2*)(gbase + (size_t)r * F + hl * 4);
            addv((const unsigned int*)&v);
        }
    };

    // self contribution: lower half only (counted once after merge)
    if (hf == 0) loadrow(gw);

    int s = d_off[gw];
    int e = d_off[gw + 1];

    for (int base = s; base < e; base += 32) {
        int cnt = e - base;
        if (cnt > 32) cnt = 32;
        int idx = (lane < cnt) ? d_csr[base + lane] : 0;  // coalesced index fetch
        int k = 0;

        auto pairs = [&](auto npc) {
            constexpr int P = decltype(npc)::value;  // pairs in flight
            int r[P];
#pragma unroll
            for (int i = 0; i < P; i++)
                r[i] = __shfl_sync(0xffffffffu, idx, k + 2 * i + hf);
            if constexpr (C == 8) {
                uint4 v[P];
#pragma unroll
                for (int i = 0; i < P; i++)
                    v[i] = *(const uint4*)(gbase + (size_t)r[i] * F + hl * 8);
#pragma unroll
                for (int i = 0; i < P; i++) addv((const unsigned int*)&v[i]);
            } else {
                uint2 v[P];
#pragma unroll
                for (int i = 0; i < P; i++)
                    v[i] = *(const uint2*)(gbase + (size_t)r[i] * F + hl * 4);
#pragma unroll
                for (int i = 0; i < P; i++) addv((const unsigned int*)&v[i]);
            }
            k += 2 * P;
        };

        while (k + 15 < cnt) pairs(Int<8>{});   // 16 edges, 8 loads in flight
        if (k + 7 < cnt) pairs(Int<4>{});       // 8 edges
        if (k + 3 < cnt) pairs(Int<2>{});       // 4 edges
        if (k + 1 < cnt) pairs(Int<1>{});       // 2 edges
        if (k < cnt) {                          // final odd edge
            int r = __shfl_sync(0xffffffffu, idx, k);
            if (hf == 0) loadrow(r);
        }
    }

    // merge the two half-warp partial sums
#pragma unroll
    for (int i = 0; i < C; i++)
        acc[i] += __shfl_xor_sync(0xffffffffu, acc[i], 16);

    float dv = d_dinv[gw];
    float o[C];
    {
        float4 b0 = *(const float4*)(bias + hl * C);
        o[0] = dv * acc[0] + b0.x;
        o[1] = dv * acc[1] + b0.y;
        o[2] = dv * acc[2] + b0.z;
        o[3] = dv * acc[3] + b0.w;
        if constexpr (C == 8) {
            float4 b1 = *(const float4*)(bias + hl * C + 4);
            o[4] = dv * acc[4] + b1.x;
            o[5] = dv * acc[5] + b1.y;
            o[6] = dv * acc[6] + b1.z;
            o[7] = dv * acc[7] + b1.w;
        }
    }
    if (RELU) {
#pragma unroll
        for (int i = 0; i < C; i++) o[i] = fmaxf(o[i], 0.f);
    }

    if (hf == 0) {  // lower half stores full row (16 lanes x C features)
        if constexpr (OUT_PARAM) {
            float* dst = Yparam + (size_t)gw * F + hl * C;
#pragma unroll
            for (int q = 0; q < C / 4; q++)
                *(float4*)(dst + 4 * q) =
                    make_float4(o[4 * q], o[4 * q + 1], o[4 * q + 2], o[4 * q + 3]);
        } else {
            __half* dst = d_bufXh + (size_t)gw * F + hl * C;
            unsigned int h[C / 2];
#pragma unroll
            for (int j = 0; j < C / 2; j++) {
                __half2 p = __floats2half2_rn(o[2 * j], o[2 * j + 1]);
                h[j] = *(unsigned int*)&p;
            }
            if constexpr (C == 8)
                *(uint4*)dst = make_uint4(h[0], h[1], h[2], h[3]);
            else
                *(uint2*)dst = make_uint2(h[0], h[1]);
        }
    }
}

// ---------------- launch ----------------
extern "C" void kernel_launch(void* const* d_in, const int* in_sizes, int n_in,
                              void* d_out, int out_size) {
    const float* x  = (const float*)d_in[0];
    const int*   ei = (const int*)d_in[1];   // int32 or int64 words; auto-detected
    const float* W1 = (const float*)d_in[2];
    const float* b1 = (const float*)d_in[3];
    const float* W2 = (const float*)d_in[4];
    const float* b2 = (const float*)d_in[5];
    const float* W3 = (const float*)d_in[6];
    const float* b3 = (const float*)d_in[7];
    const float* W4 = (const float*)d_in[8];
    const float* b4 = (const float*)d_in[9];
    float* out = (float*)d_out;

    int n = in_sizes[0] / FIN;
    int E = in_sizes[1] / 2;

    // graph build
    init_kernel<<<(n + 255) / 256, 256>>>(ei, E, n);
    hist_kernel<<<(E + 255) / 256, 256>>>(ei, E);
    int nb = (n + 511) / 512;
    scan1_kernel<<<nb, 512>>>(n);
    scan2_kernel<<<1, 512>>>(nb, n);
    scan3_kernel<<<(n + 255) / 256, 256>>>(n);
    fill_kernel<<<(E + 255) / 256, 256>>>(ei, E);

    // conversions
    int xc2 = n * FIN / 2;
    conv_x_kernel<<<(xc2 + 255) / 256, 256>>>(x, xc2);
    conv_w_all_kernel<<<112, 256>>>(W1, W2, W3, W4);

    int gemm_blocks = (n + 127) / 128;
    int agg_blocks = (n * 32 + 255) / 256;

    // layer 1
    gemm_tc_kernel<128><<<gemm_blocks, 256>>>(0, n);
    agg_kernel<128, true, false><<<agg_blocks, 256>>>(b1, nullptr, n);
    // layer 2
    gemm_tc_kernel<128><<<gemm_blocks, 256>>>(16384, n);
    agg_kernel<128, true, false><<<agg_blocks, 256>>>(b2, nullptr, n);
    // layer 3
    gemm_tc_kernel<128><<<gemm_blocks, 256>>>(32768, n);
    agg_kernel<128, true, false><<<agg_blocks, 256>>>(b3, nullptr, n);
    // layer 4 (OUT=64) -> d_out
    gemm_tc_kernel<64><<<gemm_blocks, 128>>>(49152, n);
    agg_kernel<64, false, true><<<agg_blocks, 256>>>(b4, out, n);
}